// round 6
// baseline (speedup 1.0000x reference)
#include <cuda_runtime.h>
#include <cuda_bf16.h>
#include <cstdint>
#include <cstddef>

#define CKDIM 64
#define K2    128
#define NP    4096
#define NN    8192
#define NV    1024
#define NBLK  64

// ---------------- scratch ----------------
__device__ float g_ST[(size_t)NP * NN];            // E^T[p][n], tf32-rounded (134 MB)
__device__ __nv_bfloat16 g_Qh[(size_t)NP * K2];    // [p][k] bf16 hi of [2qk*qe; -qe]
__device__ __nv_bfloat16 g_Ql[(size_t)NP * K2];    // [p][k] bf16 lo
__device__ __nv_bfloat16 g_Mh[(size_t)NN * K2];    // [n][k] bf16 hi of [mk; mk^2]
__device__ __nv_bfloat16 g_Ml[(size_t)NN * K2];    // [n][k] bf16 lo
__device__ float g_MV[(size_t)NV * NN];            // tf32-rounded mv (K-major)
__device__ float g_bsq[NP];
__device__ float g_msn[NN];
__device__ float g_part[(size_t)NBLK * NP];
__device__ float g_rinv[NP];

__device__ __forceinline__ float tf32r(float x) {
    uint32_t u;
    asm("cvt.rna.tf32.f32 %0, %1;" : "=r"(u) : "f"(x));
    return __uint_as_float(u);
}
__device__ __forceinline__ void cp16(uint32_t dst, const void* src) {
    asm volatile("cp.async.cg.shared.global [%0], [%1], 16;\n" :: "r"(dst), "l"(src));
}
__device__ __forceinline__ uint32_t smem_u32(const void* p) {
    return (uint32_t)__cvta_generic_to_shared(p);
}
#define MMA_BF16(acc, a, b)                                                          \
    asm volatile(                                                                    \
        "mma.sync.aligned.m16n8k16.row.col.f32.bf16.bf16.f32 "                       \
        "{%0,%1,%2,%3}, {%4,%5,%6,%7}, {%8,%9}, {%0,%1,%2,%3};\n"                    \
        : "+f"((acc)[0]), "+f"((acc)[1]), "+f"((acc)[2]), "+f"((acc)[3])             \
        : "r"((a)[0]), "r"((a)[1]), "r"((a)[2]), "r"((a)[3]),                        \
          "r"((b)[0]), "r"((b)[1]))
#define MMA_TF32(acc, a, b)                                                          \
    asm volatile(                                                                    \
        "mma.sync.aligned.m16n8k8.row.col.f32.tf32.tf32.f32 "                        \
        "{%0,%1,%2,%3}, {%4,%5,%6,%7}, {%8,%9}, {%0,%1,%2,%3};\n"                    \
        : "+f"((acc)[0]), "+f"((acc)[1]), "+f"((acc)[2]), "+f"((acc)[3])             \
        : "r"(__float_as_uint((a)[0])), "r"(__float_as_uint((a)[1])),                \
          "r"(__float_as_uint((a)[2])), "r"(__float_as_uint((a)[3])),                \
          "r"(__float_as_uint((b)[0])), "r"(__float_as_uint((b)[1])))

// ---------------- prep kernels ----------------
__global__ void prep_q_kernel(const float* __restrict__ qk, const float* __restrict__ qe) {
    int p = blockIdx.x * blockDim.x + threadIdx.x;
    if (p >= NP) return;
    float bsq = 0.f;
#pragma unroll
    for (int c = 0; c < CKDIM; ++c) {
        float k = qk[c * NP + p];
        float e = qe[c * NP + p];
        float b1 = 2.f * k * e;
        float b2 = -e;
        __nv_bfloat16 h1 = __float2bfloat16(b1);
        __nv_bfloat16 h2 = __float2bfloat16(b2);
        g_Qh[(size_t)p * K2 + c]         = h1;
        g_Ql[(size_t)p * K2 + c]         = __float2bfloat16(b1 - __bfloat162float(h1));
        g_Qh[(size_t)p * K2 + CKDIM + c] = h2;
        g_Ql[(size_t)p * K2 + CKDIM + c] = __float2bfloat16(b2 - __bfloat162float(h2));
        bsq = fmaf(e * k, k, bsq);
    }
    g_bsq[p] = bsq;
}

__global__ void prep_m_kernel(const float* __restrict__ mk, const float* __restrict__ ms) {
    int n = blockIdx.x * blockDim.x + threadIdx.x;
    if (n >= NN) return;
#pragma unroll
    for (int c = 0; c < CKDIM; ++c) {
        float v = mk[c * NN + n];
        float v2 = v * v;
        __nv_bfloat16 h = __float2bfloat16(v);
        __nv_bfloat16 h2 = __float2bfloat16(v2);
        g_Mh[(size_t)n * K2 + c]         = h;
        g_Ml[(size_t)n * K2 + c]         = __float2bfloat16(v - __bfloat162float(h));
        g_Mh[(size_t)n * K2 + CKDIM + c] = h2;
        g_Ml[(size_t)n * K2 + CKDIM + c] = __float2bfloat16(v2 - __bfloat162float(h2));
    }
    g_msn[n] = ms[n] * 0.125f;
}

__global__ void prep_mv_kernel(const float* __restrict__ mv) {
    size_t i = (size_t)blockIdx.x * blockDim.x + threadIdx.x;
    float4 v = ((const float4*)mv)[i];
    v.x = tf32r(v.x); v.y = tf32r(v.y); v.z = tf32r(v.z); v.w = tf32r(v.w);
    ((float4*)g_MV)[i] = v;
}

// ---------------- sim kernel: split-bf16 m16n8k16, writes E^T + row partials ------
// CTA tile: 128 p x 128 n, K2=128 in 4 chunks of 32. Tiles [128][40 bf16] x4 x2 stages.
#define STILE 5120          // bf16 elems per tile-stage (128*40)
#define SWORDS 2560         // uint32 words per tile-stage

__global__ __launch_bounds__(256) void sim_kernel() {
    extern __shared__ __nv_bfloat16 sm16[];
    const uint32_t* w32 = (const uint32_t*)sm16;
    __shared__ float red[2][128];

    const int tid  = threadIdx.x;
    const int bNn  = blockIdx.x * 128;
    const int bNp  = blockIdx.y * 128;
    const int warp = tid >> 5;
    const int lane = tid & 31;
    const int wm = (warp & 3) * 32;      // p warp tile
    const int nw = warp >> 2;
    const int wn = nw * 64;              // n warp tile
    const int g  = lane >> 2;
    const int tg = lane & 3;

    float acc[2][8][4];
#pragma unroll
    for (int i = 0; i < 2; ++i)
#pragma unroll
        for (int j = 0; j < 8; ++j)
#pragma unroll
            for (int r = 0; r < 4; ++r) acc[i][j][r] = 0.f;

    const __nv_bfloat16* gsrc[4] = {g_Qh, g_Ql, g_Mh, g_Ml};
    auto load_tiles = [&](int kt, int st) {
#pragma unroll
        for (int t = 0; t < 4; ++t) {
            int rowbase = (t < 2) ? bNp : bNn;
#pragma unroll
            for (int s = 0; s < 2; ++s) {
                int id = tid + s * 256;        // 0..511
                int r  = id >> 2;              // 0..127
                int c  = id & 3;               // 16B chunk = 8 bf16
                uint32_t dst = smem_u32(sm16) +
                               ((t * 2 + st) * STILE + r * 40 + c * 8) * 2;
                cp16(dst, &gsrc[t][(size_t)(rowbase + r) * K2 + kt * 32 + c * 8]);
            }
        }
        asm volatile("cp.async.commit_group;\n" ::);
    };

    load_tiles(0, 0);

    for (int kt = 0; kt < 4; ++kt) {
        const int cur = kt & 1;
        if (kt + 1 < 4) {
            load_tiles(kt + 1, cur ^ 1);
            asm volatile("cp.async.wait_group 1;\n" ::);
        } else {
            asm volatile("cp.async.wait_group 0;\n" ::);
        }
        __syncthreads();

        const int qh = (0 * 2 + cur) * SWORDS;
        const int ql = (1 * 2 + cur) * SWORDS;
        const int mh = (2 * 2 + cur) * SWORDS;
        const int ml = (3 * 2 + cur) * SWORDS;

#pragma unroll
        for (int ks = 0; ks < 2; ++ks) {
            const int k0 = ks * 8;   // word offset within 20-word row
            uint32_t ah[2][4], al[2][4], bh[8][2], bl[8][2];
#pragma unroll
            for (int i = 0; i < 2; ++i) {
                int r0 = (wm + 16 * i + g) * 20 + k0;
                int r8 = r0 + 8 * 20;
                ah[i][0] = w32[qh + r0 + tg];     ah[i][1] = w32[qh + r8 + tg];
                ah[i][2] = w32[qh + r0 + tg + 4]; ah[i][3] = w32[qh + r8 + tg + 4];
                al[i][0] = w32[ql + r0 + tg];     al[i][1] = w32[ql + r8 + tg];
                al[i][2] = w32[ql + r0 + tg + 4]; al[i][3] = w32[ql + r8 + tg + 4];
            }
#pragma unroll
            for (int j = 0; j < 8; ++j) {
                int nr = (wn + 8 * j + g) * 20 + k0;
                bh[j][0] = w32[mh + nr + tg]; bh[j][1] = w32[mh + nr + tg + 4];
                bl[j][0] = w32[ml + nr + tg]; bl[j][1] = w32[ml + nr + tg + 4];
            }
#pragma unroll
            for (int i = 0; i < 2; ++i)
#pragma unroll
                for (int j = 0; j < 8; ++j) {
                    MMA_BF16(acc[i][j], ah[i], bh[j]);
                    MMA_BF16(acc[i][j], al[i], bh[j]);
                    MMA_BF16(acc[i][j], ah[i], bl[j]);
                }
        }
        __syncthreads();
    }

    // epilogue: e = exp(msn[n]*(acc - bsq[p])), write E^T[p][n], row sums per p
    float bsqr[2][2];
#pragma unroll
    for (int i = 0; i < 2; ++i) {
        int r0 = bNp + wm + 16 * i + g;
        bsqr[i][0] = g_bsq[r0];
        bsqr[i][1] = g_bsq[r0 + 8];
    }
    float msv[8][2];
#pragma unroll
    for (int j = 0; j < 8; ++j) {
        int c0 = bNn + wn + 8 * j + 2 * tg;
        msv[j][0] = g_msn[c0];
        msv[j][1] = g_msn[c0 + 1];
    }
    float rsum[2][2];
    rsum[0][0] = rsum[0][1] = rsum[1][0] = rsum[1][1] = 0.f;

#pragma unroll
    for (int i = 0; i < 2; ++i) {
        int r0 = bNp + wm + 16 * i + g;
        int r1 = r0 + 8;
#pragma unroll
        for (int j = 0; j < 8; ++j) {
            int c0 = bNn + wn + 8 * j + 2 * tg;
            float e0 = tf32r(__expf(msv[j][0] * (acc[i][j][0] - bsqr[i][0])));
            float e1 = tf32r(__expf(msv[j][1] * (acc[i][j][1] - bsqr[i][0])));
            float e2 = tf32r(__expf(msv[j][0] * (acc[i][j][2] - bsqr[i][1])));
            float e3 = tf32r(__expf(msv[j][1] * (acc[i][j][3] - bsqr[i][1])));
            *(float2*)&g_ST[(size_t)r0 * NN + c0] = make_float2(e0, e1);
            *(float2*)&g_ST[(size_t)r1 * NN + c0] = make_float2(e2, e3);
            rsum[i][0] += e0 + e1;
            rsum[i][1] += e2 + e3;
        }
    }
#pragma unroll
    for (int i = 0; i < 2; ++i)
#pragma unroll
        for (int d = 0; d < 2; ++d) {
            float s = rsum[i][d];
            s += __shfl_xor_sync(0xffffffffu, s, 1);
            s += __shfl_xor_sync(0xffffffffu, s, 2);
            if (tg == 0) red[nw][wm + 16 * i + 8 * d + g] = s;
        }
    __syncthreads();
    if (tid < 128)
        g_part[(size_t)blockIdx.x * NP + bNp + tid] = red[0][tid] + red[1][tid];
}

// ---------------- rinv ----------------
__global__ void rinv_kernel() {
    int p = blockIdx.x * blockDim.x + threadIdx.x;
    float s = 0.f;
#pragma unroll
    for (int b = 0; b < NBLK; ++b) s += g_part[(size_t)b * NP + p];
    g_rinv[p] = 1.0f / s;
}

// ---------------- readout GEMM: tf32 mma.sync, CTA 128x256, warp 64x64 ----------
// out[v][p] = rinv[p] * sum_n MV[v][n] * E^T[p][n]
#define OBK   32
#define ONKT  (NN / OBK)        // 256
#define OAW   36                // row stride in fp32 words (144B, 16B-aligned)
#define OASZ  (128 * OAW * 4)   // 18432 B
#define OBSZ  (256 * OAW * 4)   // 36864 B
#define OSTG  (OASZ + OBSZ)     // 55296 B
#define OSMEM (3 * OSTG)        // 165888 B

__global__ __launch_bounds__(256, 1) void out_gemm_kernel(float* __restrict__ out) {
    extern __shared__ float Sf[];
    const int tid  = threadIdx.x;
    const int warp = tid >> 5;
    const int lane = tid & 31;
    const int bM = blockIdx.x * 128;   // v offset (x fastest -> 8 CTAs share B tile)
    const int bN = blockIdx.y * 256;   // p offset
    const int wv = (warp & 1) * 64;
    const int wp = (warp >> 1) * 64;
    const int g  = lane >> 2;
    const int tg = lane & 3;
    const uint32_t sbase = smem_u32(Sf);

    float acc[4][8][4];
#pragma unroll
    for (int i = 0; i < 4; ++i)
#pragma unroll
        for (int j = 0; j < 8; ++j)
#pragma unroll
            for (int r = 0; r < 4; ++r) acc[i][j][r] = 0.f;

    auto load_stage = [&](int kt, int st) {
        uint32_t ab = sbase + st * OSTG;
        uint32_t bb = ab + OASZ;
#pragma unroll
        for (int s = 0; s < 4; ++s) {          // A: 1024 16B chunks
            int id = tid + s * 256;
            int r = id >> 3, c = id & 7;
            cp16(ab + r * 144 + c * 16, &g_MV[(size_t)(bM + r) * NN + kt * OBK + c * 4]);
        }
#pragma unroll
        for (int s = 0; s < 8; ++s) {          // B: 2048 chunks
            int id = tid + s * 256;
            int r = id >> 3, c = id & 7;
            cp16(bb + r * 144 + c * 16, &g_ST[(size_t)(bN + r) * NN + kt * OBK + c * 4]);
        }
        asm volatile("cp.async.commit_group;\n" ::);
    };

    load_stage(0, 0);
    load_stage(1, 1);
    load_stage(2, 2);

    for (int kt = 0; kt < ONKT; ++kt) {
        if (kt < ONKT - 2)      asm volatile("cp.async.wait_group 2;\n" ::);
        else if (kt == ONKT - 2) asm volatile("cp.async.wait_group 1;\n" ::);
        else                    asm volatile("cp.async.wait_group 0;\n" ::);
        __syncthreads();

        const int st = kt % 3;
        const int abase = st * (OSTG / 4);
        const int bbase = abase + OASZ / 4;

#pragma unroll
        for (int ks = 0; ks < 4; ++ks) {
            const int k0 = ks * 8;
            float af[4][4];
#pragma unroll
            for (int i = 0; i < 4; ++i) {
                int r0 = abase + (wv + 16 * i + g) * OAW + k0;
                int r8 = r0 + 8 * OAW;
                af[i][0] = Sf[r0 + tg];     af[i][1] = Sf[r8 + tg];
                af[i][2] = Sf[r0 + tg + 4]; af[i][3] = Sf[r8 + tg + 4];
            }
            float bf[8][2];
#pragma unroll
            for (int j = 0; j < 8; ++j) {
                int nr = bbase + (wp + 8 * j + g) * OAW + k0;
                bf[j][0] = Sf[nr + tg];
                bf[j][1] = Sf[nr + tg + 4];
            }
#pragma unroll
            for (int i = 0; i < 4; ++i)
#pragma unroll
                for (int j = 0; j < 8; ++j)
                    MMA_TF32(acc[i][j], af[i], bf[j]);
        }
        __syncthreads();
        if (kt + 3 < ONKT) load_stage(kt + 3, (kt + 3) % 3);
    }

    // epilogue: scale by rinv[p]
#pragma unroll
    for (int j = 0; j < 8; ++j) {
        int c = bN + wp + 8 * j + 2 * tg;
        float r0 = g_rinv[c];
        float r1 = g_rinv[c + 1];
#pragma unroll
        for (int i = 0; i < 4; ++i) {
            int rr = bM + wv + 16 * i + g;
            *(float2*)&out[(size_t)rr * NP + c] =
                make_float2(acc[i][j][0] * r0, acc[i][j][1] * r1);
            *(float2*)&out[(size_t)(rr + 8) * NP + c] =
                make_float2(acc[i][j][2] * r0, acc[i][j][3] * r1);
        }
    }
}

// ---------------- launch ----------------
extern "C" void kernel_launch(void* const* d_in, const int* in_sizes, int n_in,
                              void* d_out, int out_size) {
    const float* qk = (const float*)d_in[0];
    const float* qe = (const float*)d_in[1];
    const float* mk = (const float*)d_in[2];
    const float* ms = (const float*)d_in[3];
    const float* mv = (const float*)d_in[4];
    float* out = (float*)d_out;

    const int SIM_SMEM = 8 * STILE * 2;   // 4 tiles x 2 stages x 5120 bf16 = 81920 B
    cudaFuncSetAttribute(sim_kernel, cudaFuncAttributeMaxDynamicSharedMemorySize, SIM_SMEM);
    cudaFuncSetAttribute(out_gemm_kernel, cudaFuncAttributeMaxDynamicSharedMemorySize, OSMEM);

    prep_q_kernel<<<NP / 256, 256>>>(qk, qe);
    prep_m_kernel<<<NN / 256, 256>>>(mk, ms);
    prep_mv_kernel<<<(NV * NN / 4) / 256, 256>>>(mv);
    sim_kernel<<<dim3(NN / 128, NP / 128), 256, SIM_SMEM>>>();
    rinv_kernel<<<NP / 256, 256>>>();
    out_gemm_kernel<<<dim3(NV / 128, NP / 256), 256, OSMEM>>>(out);
}